// round 13
// baseline (speedup 1.0000x reference)
#include <cuda_runtime.h>
#include <math.h>

#define B_  8
#define C_  3
#define H_  512
#define W_  512
#define FR_ 3
#define KS_ 7

#define TILE 32
#define HALO (TILE + 2*FR_)     // 38
#define PW   41                 // row pitch floats: (4tx + 9row) mod 32 -> conflict-free
#define NT   256
#define NBLOCKS (B_ * (H_/TILE) * (W_/TILE))   // 2048

__device__ float        g_partials[NBLOCKS];
__device__ unsigned int g_done = 0;   // self-resetting via atomicInc wrap

__device__ __forceinline__ float ex2f(float x) {
    float r; asm("ex2.approx.ftz.f32 %0,%1;" : "=f"(r) : "f"(x)); return r;
}

__device__ __forceinline__ int reflect_idx(int i, int n) {
    if (i < 0) i = -i;
    if (i >= n) i = 2*n - 2 - i;
    return i;
}

#define LOG2A  (-2.65056562f)       // log2(1/sumG^2)
#define GLOG   (-0.72134751f)       // log2 Gaussian coeff: -d^2 * 0.72134751
#define SC_    (-72.13475204f)      // -50*log2(e)

__global__ __launch_bounds__(NT, 5)
void blt_loss_kernel(const float* __restrict__ in, float* __restrict__ out)
{
    __shared__ float tile[C_][HALO][PW];
    __shared__ float warp_sums[NT / 32];
    __shared__ int   is_last;

    const int tid = threadIdx.x;
    const int x0b = blockIdx.x * TILE;
    const int y0b = blockIdx.y * TILE;
    const int b   = blockIdx.z;

    // ---- load tile + halo (reflect) ----
    {
        const float* base = in + (size_t)b * C_ * H_ * W_;
        for (int idx = tid; idx < C_ * HALO * HALO; idx += NT) {
            int c   = idx / (HALO * HALO);
            int rem = idx - c * (HALO * HALO);
            int iy  = rem / HALO;
            int ix  = rem - iy * HALO;
            int gy  = reflect_idx(y0b - FR_ + iy, H_);
            int gx  = reflect_idx(x0b - FR_ + ix, W_);
            tile[c][iy][ix] = base[(c * H_ + gy) * W_ + gx];
        }
    }
    __syncthreads();

    // Thread -> 4 consecutive x pixels in one row
    const int ty = tid >> 3;            // 0..31
    const int xx = (tid & 7) * 4;       // pixel-in-tile base; tile col = xx+3+i

    // centers (12 floats)
    float cc0[4], cc1[4], cc2[4];
    #pragma unroll
    for (int i = 0; i < 4; i++) {
        cc0[i] = tile[0][ty + FR_][xx + FR_ + i];
        cc1[i] = tile[1][ty + FR_][xx + FR_ + i];
        cc2[i] = tile[2][ty + FR_][xx + FR_ + i];
    }

    float acc0 = 0.f, acc1 = 0.f, acc2 = 0.f, acc3 = 0.f;

    // ===== MAIN: 24 positive-half taps, weight 2 folded into lc (+1.0 log2) =====
    #pragma unroll
    for (int k = FR_; k < KS_; k++) {
        const int row = ty + k;
        const int dy  = k - FR_;
        const int l0  = (k == FR_) ? (FR_ + 1) : 0;

        #pragma unroll
        for (int l = 0; l < KS_; l++) {
            if (l < l0) continue;
            const int dx = l - FR_;
            const float lc = LOG2A + 1.0f + GLOG * (float)(dy*dy + dx*dx);

            #pragma unroll
            for (int i = 0; i < 4; i++) {
                const float n0 = tile[0][row][xx + l + i];
                const float n1 = tile[1][row][xx + l + i];
                const float n2 = tile[2][row][xx + l + i];
                const float d0 = cc0[i] - n0;
                const float d1 = cc1[i] - n1;
                const float d2 = cc2[i] - n2;
                const float s  = fmaf(d2, d2, fmaf(d1, d1, d0 * d0));
                const float e  = ex2f(fmaf(s, SC_, lc));
                const float L  = (fabsf(d0) + fabsf(d1)) + fabsf(d2);
                if      (i == 0) acc0 = fmaf(L, e, acc0);
                else if (i == 1) acc1 = fmaf(L, e, acc1);
                else if (i == 2) acc2 = fmaf(L, e, acc2);
                else             acc3 = fmaf(L, e, acc3);
            }
        }
    }

    // ===== CORRECTION: only border blocks; exact fix for reflecting taps =====
    if (x0b == 0 || y0b == 0 || x0b == W_ - TILE || y0b == H_ - TILE) {
        const int ys = y0b + ty;
        const int xa = x0b + xx;

        #pragma unroll 1
        for (int dy = -FR_; dy <= FR_; dy++) {
            const int  row = ty + FR_ + dy;
            const bool inY = (unsigned)(ys + dy) < (unsigned)H_;
            #pragma unroll 1
            for (int dx = -FR_; dx <= FR_; dx++) {
                if (dy == 0 && dx == 0) continue;

                bool inb[4];
                bool all_in = true;
                #pragma unroll
                for (int i = 0; i < 4; i++) {
                    inb[i] = inY && ((unsigned)(xa + i + dx) < (unsigned)W_);
                    all_in = all_in && inb[i];
                }
                if (all_in) continue;   // nothing reflects here

                const bool inH = (dy > 0) || (dy == 0 && dx > 0);
                const float sg = inH ? -1.0f : 1.0f;   // 2x->1x, or 0x->1x
                const float lc = LOG2A + GLOG * (float)(dy*dy + dx*dx);  // 1x weight
                const int   l  = dx + FR_;

                #pragma unroll
                for (int i = 0; i < 4; i++) {
                    const float m  = inb[i] ? 0.0f : sg;
                    const float n0 = tile[0][row][xx + l + i];
                    const float n1 = tile[1][row][xx + l + i];
                    const float n2 = tile[2][row][xx + l + i];
                    const float d0 = cc0[i] - n0;
                    const float d1 = cc1[i] - n1;
                    const float d2 = cc2[i] - n2;
                    const float s  = fmaf(d2, d2, fmaf(d1, d1, d0 * d0));
                    const float e  = ex2f(fmaf(s, SC_, lc));
                    const float L  = (fabsf(d0) + fabsf(d1)) + fabsf(d2);
                    const float v  = L * e;
                    if      (i == 0) acc0 = fmaf(v, m, acc0);
                    else if (i == 1) acc1 = fmaf(v, m, acc1);
                    else if (i == 2) acc2 = fmaf(v, m, acc2);
                    else             acc3 = fmaf(v, m, acc3);
                }
            }
        }
    }

    // ---- reduce: thread -> warp -> block ----
    float acc = (acc0 + acc1) + (acc2 + acc3);

    #pragma unroll
    for (int ofs = 16; ofs > 0; ofs >>= 1)
        acc += __shfl_down_sync(0xffffffffu, acc, ofs);

    if ((tid & 31) == 0) warp_sums[tid >> 5] = acc;
    __syncthreads();

    if (tid == 0) {
        float bs = 0.0f;
        #pragma unroll
        for (int wi = 0; wi < NT / 32; wi++) bs += warp_sums[wi];
        const int bidx = (blockIdx.z * gridDim.y + blockIdx.y) * gridDim.x + blockIdx.x;
        g_partials[bidx] = bs;
        __threadfence();
        unsigned int old = atomicInc(&g_done, NBLOCKS - 1);  // wraps to 0: self-reset
        is_last = (old == NBLOCKS - 1);
    }
    __syncthreads();

    // ---- last block: final deterministic reduce ----
    if (is_last) {
        float s = 0.0f;
        for (int i = tid; i < NBLOCKS; i += NT)
            s += __ldcg(&g_partials[i]);

        #pragma unroll
        for (int ofs = 16; ofs > 0; ofs >>= 1)
            s += __shfl_down_sync(0xffffffffu, s, ofs);

        if ((tid & 31) == 0) warp_sums[tid >> 5] = s;
        __syncthreads();

        if (tid == 0) {
            float total = 0.0f;
            #pragma unroll
            for (int wi = 0; wi < NT / 32; wi++) total += warp_sums[wi];
            out[0] = total * (1.0f / (float)((size_t)B_ * C_ * H_ * W_));
        }
    }
}

extern "C" void kernel_launch(void* const* d_in, const int* in_sizes, int n_in,
                              void* d_out, int out_size)
{
    const float* in = (const float*)d_in[0];
    float* out = (float*)d_out;

    dim3 grid(W_ / TILE, H_ / TILE, B_);   // 16,16,8
    blt_loss_kernel<<<grid, NT>>>(in, out);
}

// round 14
// speedup vs baseline: 1.0273x; 1.0273x over previous
#include <cuda_runtime.h>
#include <math.h>

#define B_  8
#define C_  3
#define H_  512
#define W_  512
#define FR_ 3
#define KS_ 7

#define TILE 32
#define HALO (TILE + 2*FR_)     // 38
#define P2   21                 // row pitch in u64 units (42 floats)
#define NT   256
#define NBLOCKS (B_ * (H_/TILE) * (W_/TILE))   // 2048

typedef unsigned long long u64;

__device__ float        g_partials[NBLOCKS];
__device__ unsigned int g_done = 0;   // self-resetting via atomicInc wrap

union F2 { u64 u; float2 f; };

// ---- f32x2 packed helpers (sm_103a) ----
__device__ __forceinline__ u64 mul2(u64 a, u64 b) {
    u64 r; asm("mul.rn.f32x2 %0,%1,%2;" : "=l"(r) : "l"(a), "l"(b)); return r;
}
__device__ __forceinline__ u64 fma2(u64 a, u64 b, u64 c) {
    u64 r; asm("fma.rn.f32x2 %0,%1,%2,%3;" : "=l"(r) : "l"(a), "l"(b), "l"(c)); return r;
}
__device__ __forceinline__ float ex2f(float x) {
    float r; asm("ex2.approx.ftz.f32 %0,%1;" : "=f"(r) : "f"(x)); return r;
}
__device__ __forceinline__ u64 bc2(float x) {   // compile-time broadcast
    unsigned int u = __float_as_uint(x);
    return ((u64)u << 32) | (u64)u;
}

__device__ __forceinline__ int reflect_idx(int i, int n) {
    if (i < 0) i = -i;
    if (i >= n) i = 2*n - 2 - i;
    return i;
}

// exp(-r2/2) for r2 in the 7x7 stencil (compile-time folded)
__device__ __forceinline__ constexpr float gexp(int r2) {
    switch (r2) {
        case 1:  return 0.60653066f;
        case 2:  return 0.36787944f;
        case 4:  return 0.13533528f;
        case 5:  return 0.08208500f;
        case 8:  return 0.018315639f;
        case 9:  return 0.011108997f;
        case 10: return 0.0067379470f;
        case 13: return 0.0015034392f;
        case 18: return 1.2340980e-4f;
        default: return 0.0f;
    }
}
#define INVS2 0.15924114f          // 1/sumG^2

__global__ __launch_bounds__(NT, 5)
void blt_loss_kernel(const float* __restrict__ in, float* __restrict__ out)
{
    // tA: tile; tB: tile shifted left one float. All tap pairs -> aligned LDS.64.
    __shared__ u64 tA[C_][HALO][P2];
    __shared__ u64 tB[C_][HALO][P2];
    __shared__ float warp_sums[NT / 32];
    __shared__ int   is_last;

    const int tid = threadIdx.x;
    const int x0b = blockIdx.x * TILE;
    const int y0b = blockIdx.y * TILE;
    const int b   = blockIdx.z;

    // ---- load tile + halo (reflect), write both copies ----
    {
        float* fA = (float*)tA;
        float* fB = (float*)tB;
        const float* base = in + (size_t)b * C_ * H_ * W_;
        for (int idx = tid; idx < C_ * HALO * HALO; idx += NT) {
            int c   = idx / (HALO * HALO);
            int rem = idx - c * (HALO * HALO);
            int iy  = rem / HALO;
            int ix  = rem - iy * HALO;
            int gy  = reflect_idx(y0b - FR_ + iy, H_);
            int gx  = reflect_idx(x0b - FR_ + ix, W_);
            float v = base[(c * H_ + gy) * W_ + gx];
            int off = (c * HALO + iy) * (2 * P2);
            fA[off + ix] = v;
            if (ix > 0) fB[off + ix - 1] = v;
        }
    }
    __syncthreads();

    // Thread -> 4 consecutive x pixels in one row (2 packed pairs)
    const int ty = tid >> 3;            // 0..31
    const int h  = (tid & 7) * 2;       // u64 base index

    const u64 cA0 = tB[0][ty + FR_][h + 1];
    const u64 cA1 = tB[1][ty + FR_][h + 1];
    const u64 cA2 = tB[2][ty + FR_][h + 1];
    const u64 cB0 = tB[0][ty + FR_][h + 2];
    const u64 cB1 = tB[1][ty + FR_][h + 2];
    const u64 cB2 = tB[2][ty + FR_][h + 2];

    const u64 SC2  = bc2(-72.13475204f);   // -50*log2(e)
    const u64 NEG1 = bc2(-1.0f);

    // 4 scalar accumulators (lane x parity); A and B pairs share them.
    float ac_l0 = 0.f, ac_h0 = 0.f, ac_l1 = 0.f, ac_h1 = 0.f;

    // ===== MAIN: 24 positive-half taps; weight 2*invS2*gauss as scalar imm =====
    #pragma unroll
    for (int k = FR_; k < KS_; k++) {
        const int row = ty + k;
        const int dy  = k - FR_;
        const int l0  = (k == FR_) ? (FR_ + 1) : 0;

        #pragma unroll
        for (int l = 0; l < KS_; l++) {
            if (l < l0) continue;
            const int dx = l - FR_;
            const float Kw = 2.0f * INVS2 * gexp(dy*dy + dx*dx);  // folded literal
            const int   j  = l >> 1;

            u64 nA0 = (l & 1) ? tB[0][row][h + j] : tA[0][row][h + j];
            u64 nA1 = (l & 1) ? tB[1][row][h + j] : tA[1][row][h + j];
            u64 nA2 = (l & 1) ? tB[2][row][h + j] : tA[2][row][h + j];
            u64 nB0 = (l & 1) ? tB[0][row][h + j + 1] : tA[0][row][h + j + 1];
            u64 nB1 = (l & 1) ? tB[1][row][h + j + 1] : tA[1][row][h + j + 1];
            u64 nB2 = (l & 1) ? tB[2][row][h + j + 1] : tA[2][row][h + j + 1];

            { // pair A
                u64 d0 = fma2(nA0, NEG1, cA0);
                u64 d1 = fma2(nA1, NEG1, cA1);
                u64 d2 = fma2(nA2, NEG1, cA2);
                u64 s  = fma2(d2, d2, fma2(d1, d1, mul2(d0, d0)));
                F2 tf;  tf.u = mul2(s, SC2);
                float el = ex2f(tf.f.x) * Kw;    // FMUL-imm (rt=1)
                float eh = ex2f(tf.f.y) * Kw;
                F2 f0, f1, f2; f0.u = d0; f1.u = d1; f2.u = d2;
                float Ll = fabsf(f0.f.x) + fabsf(f1.f.x) + fabsf(f2.f.x);
                float Lh = fabsf(f0.f.y) + fabsf(f1.f.y) + fabsf(f2.f.y);
                if (l & 1) { ac_l1 = fmaf(Ll, el, ac_l1); ac_h1 = fmaf(Lh, eh, ac_h1); }
                else       { ac_l0 = fmaf(Ll, el, ac_l0); ac_h0 = fmaf(Lh, eh, ac_h0); }
            }
            { // pair B
                u64 d0 = fma2(nB0, NEG1, cB0);
                u64 d1 = fma2(nB1, NEG1, cB1);
                u64 d2 = fma2(nB2, NEG1, cB2);
                u64 s  = fma2(d2, d2, fma2(d1, d1, mul2(d0, d0)));
                F2 tf;  tf.u = mul2(s, SC2);
                float el = ex2f(tf.f.x) * Kw;
                float eh = ex2f(tf.f.y) * Kw;
                F2 f0, f1, f2; f0.u = d0; f1.u = d1; f2.u = d2;
                float Ll = fabsf(f0.f.x) + fabsf(f1.f.x) + fabsf(f2.f.x);
                float Lh = fabsf(f0.f.y) + fabsf(f1.f.y) + fabsf(f2.f.y);
                if (l & 1) { ac_l1 = fmaf(Ll, el, ac_l1); ac_h1 = fmaf(Lh, eh, ac_h1); }
                else       { ac_l0 = fmaf(Ll, el, ac_l0); ac_h0 = fmaf(Lh, eh, ac_h0); }
            }
        }
    }

    // ===== CORRECTION: only border blocks; exact fix for reflecting taps =====
    if (x0b == 0 || y0b == 0 || x0b == W_ - TILE || y0b == H_ - TILE) {
        const int ys = y0b + ty;
        const int xa = x0b + 2 * h;

        #pragma unroll 1
        for (int dy = -FR_; dy <= FR_; dy++) {
            const int  row = ty + FR_ + dy;
            const bool inY = (unsigned)(ys + dy) < (unsigned)H_;
            #pragma unroll 1
            for (int dx = -FR_; dx <= FR_; dx++) {
                if (dy == 0 && dx == 0) continue;
                const bool in0 = inY && ((unsigned)(xa + dx)     < (unsigned)W_);
                const bool in1 = inY && ((unsigned)(xa + 1 + dx) < (unsigned)W_);
                const bool in2 = inY && ((unsigned)(xa + 2 + dx) < (unsigned)W_);
                const bool in3 = inY && ((unsigned)(xa + 3 + dx) < (unsigned)W_);
                if (in0 & in1 & in2 & in3) continue;

                const bool inH = (dy > 0) || (dy == 0 && dx > 0);
                const float sg = inH ? -1.0f : 1.0f;
                const float m0 = in0 ? 0.0f : sg;
                const float m1 = in1 ? 0.0f : sg;
                const float m2f = in2 ? 0.0f : sg;
                const float m3 = in3 ? 0.0f : sg;

                // 1x weight (correction), runtime r2 -> use exp2 path
                const float Kc = INVS2 * exp2f(-0.72134751f * (float)(dy*dy + dx*dx));

                const int l = dx + FR_;
                const int j = l >> 1;
                u64 nA0, nA1, nA2, nB0, nB1, nB2;
                if (l & 1) {
                    nA0 = tB[0][row][h+j];   nA1 = tB[1][row][h+j];   nA2 = tB[2][row][h+j];
                    nB0 = tB[0][row][h+j+1]; nB1 = tB[1][row][h+j+1]; nB2 = tB[2][row][h+j+1];
                } else {
                    nA0 = tA[0][row][h+j];   nA1 = tA[1][row][h+j];   nA2 = tA[2][row][h+j];
                    nB0 = tA[0][row][h+j+1]; nB1 = tA[1][row][h+j+1]; nB2 = tA[2][row][h+j+1];
                }

                { // pair A
                    u64 d0 = fma2(nA0, NEG1, cA0);
                    u64 d1 = fma2(nA1, NEG1, cA1);
                    u64 d2 = fma2(nA2, NEG1, cA2);
                    u64 s  = fma2(d2, d2, fma2(d1, d1, mul2(d0, d0)));
                    F2 tf;  tf.u = mul2(s, SC2);
                    float el = ex2f(tf.f.x) * Kc;
                    float eh = ex2f(tf.f.y) * Kc;
                    F2 f0, f1, f2; f0.u = d0; f1.u = d1; f2.u = d2;
                    float Ll = fabsf(f0.f.x) + fabsf(f1.f.x) + fabsf(f2.f.x);
                    float Lh = fabsf(f0.f.y) + fabsf(f1.f.y) + fabsf(f2.f.y);
                    ac_l0 = fmaf(Ll * el, m0, ac_l0);
                    ac_h0 = fmaf(Lh * eh, m1, ac_h0);
                }
                { // pair B
                    u64 d0 = fma2(nB0, NEG1, cB0);
                    u64 d1 = fma2(nB1, NEG1, cB1);
                    u64 d2 = fma2(nB2, NEG1, cB2);
                    u64 s  = fma2(d2, d2, fma2(d1, d1, mul2(d0, d0)));
                    F2 tf;  tf.u = mul2(s, SC2);
                    float el = ex2f(tf.f.x) * Kc;
                    float eh = ex2f(tf.f.y) * Kc;
                    F2 f0, f1, f2; f0.u = d0; f1.u = d1; f2.u = d2;
                    float Ll = fabsf(f0.f.x) + fabsf(f1.f.x) + fabsf(f2.f.x);
                    float Lh = fabsf(f0.f.y) + fabsf(f1.f.y) + fabsf(f2.f.y);
                    ac_l1 = fmaf(Ll * el, m2f, ac_l1);
                    ac_h1 = fmaf(Lh * eh, m3, ac_h1);
                }
            }
        }
    }

    // ---- reduce: thread -> warp -> block ----
    float acc = (ac_l0 + ac_h0) + (ac_l1 + ac_h1);

    #pragma unroll
    for (int ofs = 16; ofs > 0; ofs >>= 1)
        acc += __shfl_down_sync(0xffffffffu, acc, ofs);

    if ((tid & 31) == 0) warp_sums[tid >> 5] = acc;
    __syncthreads();

    if (tid == 0) {
        float bs = 0.0f;
        #pragma unroll
        for (int wi = 0; wi < NT / 32; wi++) bs += warp_sums[wi];
        const int bidx = (blockIdx.z * gridDim.y + blockIdx.y) * gridDim.x + blockIdx.x;
        g_partials[bidx] = bs;
        __threadfence();
        unsigned int old = atomicInc(&g_done, NBLOCKS - 1);  // wraps to 0: self-reset
        is_last = (old == NBLOCKS - 1);
    }
    __syncthreads();

    // ---- last block: final deterministic reduce ----
    if (is_last) {
        float s = 0.0f;
        for (int i = tid; i < NBLOCKS; i += NT)
            s += __ldcg(&g_partials[i]);

        #pragma unroll
        for (int ofs = 16; ofs > 0; ofs >>= 1)
            s += __shfl_down_sync(0xffffffffu, s, ofs);

        if ((tid & 31) == 0) warp_sums[tid >> 5] = s;
        __syncthreads();

        if (tid == 0) {
            float total = 0.0f;
            #pragma unroll
            for (int wi = 0; wi < NT / 32; wi++) total += warp_sums[wi];
            out[0] = total * (1.0f / (float)((size_t)B_ * C_ * H_ * W_));
        }
    }
}

extern "C" void kernel_launch(void* const* d_in, const int* in_sizes, int n_in,
                              void* d_out, int out_size)
{
    const float* in = (const float*)d_in[0];
    float* out = (float*)d_out;

    dim3 grid(W_ / TILE, H_ / TILE, B_);   // 16,16,8
    blt_loss_kernel<<<grid, NT>>>(in, out);
}

// round 15
// speedup vs baseline: 1.1182x; 1.0885x over previous
#include <cuda_runtime.h>
#include <math.h>

#define B_  8
#define C_  3
#define H_  512
#define W_  512
#define FR_ 3
#define KS_ 7

#define TILE 32
#define HALO (TILE + 2*FR_)     // 38
#define P2   21                 // row pitch in u64 units (42 floats)
#define NT   256
#define NBLOCKS (B_ * (H_/TILE) * (W_/TILE))   // 2048

// flat smem: copy 0 = tA (tile), copy 1 = tB (shifted left one float)
#define CPY  (C_ * HALO * P2)          // u64s per copy
#define OFFA(c,k,j) (((c)*HALO + (k))*P2 + (j))
#define OFFB(c,k,j) (CPY + ((c)*HALO + (k))*P2 + (j))

typedef unsigned long long u64;

__device__ float        g_partials[NBLOCKS];
__device__ unsigned int g_done = 0;   // self-resetting via atomicInc wrap

// ---- f32x2 packed helpers (sm_103a) ----
__device__ __forceinline__ void upk2(u64 v, float& a, float& b) {
    asm("mov.b64 {%0,%1}, %2;" : "=f"(a), "=f"(b) : "l"(v));
}
__device__ __forceinline__ u64 mul2(u64 a, u64 b) {
    u64 r; asm("mul.rn.f32x2 %0,%1,%2;" : "=l"(r) : "l"(a), "l"(b)); return r;
}
__device__ __forceinline__ u64 fma2(u64 a, u64 b, u64 c) {
    u64 r; asm("fma.rn.f32x2 %0,%1,%2,%3;" : "=l"(r) : "l"(a), "l"(b), "l"(c)); return r;
}
__device__ __forceinline__ float ex2f(float x) {
    float r; asm("ex2.approx.ftz.f32 %0,%1;" : "=f"(r) : "f"(x)); return r;
}
__device__ __forceinline__ u64 bc2(float x) {   // compile-time broadcast
    unsigned int u = __float_as_uint(x);
    return ((u64)u << 32) | (u64)u;
}

__device__ __forceinline__ int reflect_idx(int i, int n) {
    if (i < 0) i = -i;
    if (i >= n) i = 2*n - 2 - i;
    return i;
}

#define LOG2A  (-2.65056562f)       // log2(1/sumG^2)
#define GLOG   (-0.72134751f)       // log2 Gaussian coeff: -d^2 * 0.72134751

__global__ __launch_bounds__(NT, 5)
void blt_loss_kernel(const float* __restrict__ in, float* __restrict__ out)
{
    __shared__ u64 smem[2 * CPY];
    __shared__ float warp_sums[NT / 32];
    __shared__ int   is_last;

    const int tid = threadIdx.x;
    const int x0b = blockIdx.x * TILE;
    const int y0b = blockIdx.y * TILE;
    const int b   = blockIdx.z;

    // ---- load tile + halo (reflect), write both copies ----
    {
        float* fA = (float*)smem;              // copy 0
        float* fB = (float*)(smem + CPY);      // copy 1 (shifted)
        const float* base = in + (size_t)b * C_ * H_ * W_;
        for (int idx = tid; idx < C_ * HALO * HALO; idx += NT) {
            int c   = idx / (HALO * HALO);
            int rem = idx - c * (HALO * HALO);
            int iy  = rem / HALO;
            int ix  = rem - iy * HALO;
            int gy  = reflect_idx(y0b - FR_ + iy, H_);
            int gx  = reflect_idx(x0b - FR_ + ix, W_);
            float v = base[(c * H_ + gy) * W_ + gx];
            int off = (c * HALO + iy) * (2 * P2);
            fA[off + ix] = v;
            if (ix > 0) fB[off + ix - 1] = v;
        }
    }
    __syncthreads();

    // Thread -> 4 consecutive x pixels in one row (2 packed pairs)
    const int ty = tid >> 3;            // 0..31
    const int h  = (tid & 7) * 2;       // u64 base index

    // ONE per-thread base pointer; ALL tap loads are [base + compile-time imm]
    const u64* __restrict__ bp = smem + ty * P2 + h;

    const u64 cA0 = bp[OFFB(0, FR_, 1)];
    const u64 cA1 = bp[OFFB(1, FR_, 1)];
    const u64 cA2 = bp[OFFB(2, FR_, 1)];
    const u64 cB0 = bp[OFFB(0, FR_, 2)];
    const u64 cB1 = bp[OFFB(1, FR_, 2)];
    const u64 cB2 = bp[OFFB(2, FR_, 2)];

    const u64 SC2  = bc2(-72.13475204f);   // -50*log2(e)
    const u64 NEG1 = bc2(-1.0f);

    // 4 scalar accumulators (lane x parity); A and B pairs share them.
    float ac_l0 = 0.f, ac_h0 = 0.f, ac_l1 = 0.f, ac_h1 = 0.f;

    // ===== MAIN: 24 positive-half taps, weight 2 folded into lc (+1.0 log2) =====
    #pragma unroll
    for (int k = FR_; k < KS_; k++) {
        const int dy = k - FR_;
        const int l0 = (k == FR_) ? (FR_ + 1) : 0;

        #pragma unroll
        for (int l = 0; l < KS_; l++) {
            if (l < l0) continue;
            const int dx = l - FR_;
            const float lc  = LOG2A + 1.0f + GLOG * (float)(dy*dy + dx*dx);
            const u64   lc2 = bc2(lc);
            const int   j   = l >> 1;

            // all indices compile-time constants -> LDS.64 [Rbase+imm]
            u64 nA0 = (l & 1) ? bp[OFFB(0,k,j)] : bp[OFFA(0,k,j)];
            u64 nA1 = (l & 1) ? bp[OFFB(1,k,j)] : bp[OFFA(1,k,j)];
            u64 nA2 = (l & 1) ? bp[OFFB(2,k,j)] : bp[OFFA(2,k,j)];
            u64 nB0 = (l & 1) ? bp[OFFB(0,k,j+1)] : bp[OFFA(0,k,j+1)];
            u64 nB1 = (l & 1) ? bp[OFFB(1,k,j+1)] : bp[OFFA(1,k,j+1)];
            u64 nB2 = (l & 1) ? bp[OFFB(2,k,j+1)] : bp[OFFA(2,k,j+1)];

            { // pair A
                u64 d0 = fma2(nA0, NEG1, cA0);
                u64 d1 = fma2(nA1, NEG1, cA1);
                u64 d2 = fma2(nA2, NEG1, cA2);
                u64 s  = fma2(d2, d2, fma2(d1, d1, mul2(d0, d0)));
                u64 t  = fma2(s, SC2, lc2);
                float tl, th;   upk2(t, tl, th);
                float el = ex2f(tl), eh = ex2f(th);
                float d0l,d0h,d1l,d1h,d2l,d2h;
                upk2(d0, d0l, d0h); upk2(d1, d1l, d1h); upk2(d2, d2l, d2h);
                float Ll = fabsf(d0l) + fabsf(d1l) + fabsf(d2l);
                float Lh = fabsf(d0h) + fabsf(d1h) + fabsf(d2h);
                if (l & 1) { ac_l1 = fmaf(Ll, el, ac_l1); ac_h1 = fmaf(Lh, eh, ac_h1); }
                else       { ac_l0 = fmaf(Ll, el, ac_l0); ac_h0 = fmaf(Lh, eh, ac_h0); }
            }
            { // pair B
                u64 d0 = fma2(nB0, NEG1, cB0);
                u64 d1 = fma2(nB1, NEG1, cB1);
                u64 d2 = fma2(nB2, NEG1, cB2);
                u64 s  = fma2(d2, d2, fma2(d1, d1, mul2(d0, d0)));
                u64 t  = fma2(s, SC2, lc2);
                float tl, th;   upk2(t, tl, th);
                float el = ex2f(tl), eh = ex2f(th);
                float d0l,d0h,d1l,d1h,d2l,d2h;
                upk2(d0, d0l, d0h); upk2(d1, d1l, d1h); upk2(d2, d2l, d2h);
                float Ll = fabsf(d0l) + fabsf(d1l) + fabsf(d2l);
                float Lh = fabsf(d0h) + fabsf(d1h) + fabsf(d2h);
                if (l & 1) { ac_l1 = fmaf(Ll, el, ac_l1); ac_h1 = fmaf(Lh, eh, ac_h1); }
                else       { ac_l0 = fmaf(Ll, el, ac_l0); ac_h0 = fmaf(Lh, eh, ac_h0); }
            }
        }
    }

    // ===== CORRECTION: only border blocks; exact fix for reflecting taps =====
    if (x0b == 0 || y0b == 0 || x0b == W_ - TILE || y0b == H_ - TILE) {
        const int ys = y0b + ty;
        const int xa = x0b + 2 * h;

        #pragma unroll 1
        for (int dy = -FR_; dy <= FR_; dy++) {
            const int  k   = FR_ + dy;
            const bool inY = (unsigned)(ys + dy) < (unsigned)H_;
            #pragma unroll 1
            for (int dx = -FR_; dx <= FR_; dx++) {
                if (dy == 0 && dx == 0) continue;
                const bool in0 = inY && ((unsigned)(xa + dx)     < (unsigned)W_);
                const bool in1 = inY && ((unsigned)(xa + 1 + dx) < (unsigned)W_);
                const bool in2 = inY && ((unsigned)(xa + 2 + dx) < (unsigned)W_);
                const bool in3 = inY && ((unsigned)(xa + 3 + dx) < (unsigned)W_);
                if (in0 & in1 & in2 & in3) continue;

                const bool inH = (dy > 0) || (dy == 0 && dx > 0);
                const float sg = inH ? -1.0f : 1.0f;
                const float m0 = in0 ? 0.0f : sg;
                const float m1 = in1 ? 0.0f : sg;
                const float m2f = in2 ? 0.0f : sg;
                const float m3 = in3 ? 0.0f : sg;

                const float lc  = LOG2A + GLOG * (float)(dy*dy + dx*dx);  // 1x weight
                const u64   lc2 = bc2(lc);

                const int l   = dx + FR_;
                const int j   = l >> 1;
                const int cp  = (l & 1) ? CPY : 0;    // copy select (runtime ok here)
                const u64 nA0 = bp[cp + (0*HALO + k)*P2 + j];
                const u64 nA1 = bp[cp + (1*HALO + k)*P2 + j];
                const u64 nA2 = bp[cp + (2*HALO + k)*P2 + j];
                const u64 nB0 = bp[cp + (0*HALO + k)*P2 + j + 1];
                const u64 nB1 = bp[cp + (1*HALO + k)*P2 + j + 1];
                const u64 nB2 = bp[cp + (2*HALO + k)*P2 + j + 1];

                { // pair A
                    u64 d0 = fma2(nA0, NEG1, cA0);
                    u64 d1 = fma2(nA1, NEG1, cA1);
                    u64 d2 = fma2(nA2, NEG1, cA2);
                    u64 s  = fma2(d2, d2, fma2(d1, d1, mul2(d0, d0)));
                    u64 t  = fma2(s, SC2, lc2);
                    float tl, th; upk2(t, tl, th);
                    float el = ex2f(tl), eh = ex2f(th);
                    float d0l,d0h,d1l,d1h,d2l,d2h;
                    upk2(d0, d0l, d0h); upk2(d1, d1l, d1h); upk2(d2, d2l, d2h);
                    float Ll = fabsf(d0l) + fabsf(d1l) + fabsf(d2l);
                    float Lh = fabsf(d0h) + fabsf(d1h) + fabsf(d2h);
                    ac_l0 = fmaf(Ll * el, m0, ac_l0);
                    ac_h0 = fmaf(Lh * eh, m1, ac_h0);
                }
                { // pair B
                    u64 d0 = fma2(nB0, NEG1, cB0);
                    u64 d1 = fma2(nB1, NEG1, cB1);
                    u64 d2 = fma2(nB2, NEG1, cB2);
                    u64 s  = fma2(d2, d2, fma2(d1, d1, mul2(d0, d0)));
                    u64 t  = fma2(s, SC2, lc2);
                    float tl, th; upk2(t, tl, th);
                    float el = ex2f(tl), eh = ex2f(th);
                    float d0l,d0h,d1l,d1h,d2l,d2h;
                    upk2(d0, d0l, d0h); upk2(d1, d1l, d1h); upk2(d2, d2l, d2h);
                    float Ll = fabsf(d0l) + fabsf(d1l) + fabsf(d2l);
                    float Lh = fabsf(d0h) + fabsf(d1h) + fabsf(d2h);
                    ac_l1 = fmaf(Ll * el, m2f, ac_l1);
                    ac_h1 = fmaf(Lh * eh, m3, ac_h1);
                }
            }
        }
    }

    // ---- reduce: thread -> warp -> block ----
    float acc = (ac_l0 + ac_h0) + (ac_l1 + ac_h1);

    #pragma unroll
    for (int ofs = 16; ofs > 0; ofs >>= 1)
        acc += __shfl_down_sync(0xffffffffu, acc, ofs);

    if ((tid & 31) == 0) warp_sums[tid >> 5] = acc;
    __syncthreads();

    if (tid == 0) {
        float bs = 0.0f;
        #pragma unroll
        for (int wi = 0; wi < NT / 32; wi++) bs += warp_sums[wi];
        const int bidx = (blockIdx.z * gridDim.y + blockIdx.y) * gridDim.x + blockIdx.x;
        g_partials[bidx] = bs;
        __threadfence();
        unsigned int old = atomicInc(&g_done, NBLOCKS - 1);  // wraps to 0: self-reset
        is_last = (old == NBLOCKS - 1);
    }
    __syncthreads();

    // ---- last block: final deterministic reduce ----
    if (is_last) {
        float s = 0.0f;
        for (int i = tid; i < NBLOCKS; i += NT)
            s += __ldcg(&g_partials[i]);

        #pragma unroll
        for (int ofs = 16; ofs > 0; ofs >>= 1)
            s += __shfl_down_sync(0xffffffffu, s, ofs);

        if ((tid & 31) == 0) warp_sums[tid >> 5] = s;
        __syncthreads();

        if (tid == 0) {
            float total = 0.0f;
            #pragma unroll
            for (int wi = 0; wi < NT / 32; wi++) total += warp_sums[wi];
            out[0] = total * (1.0f / (float)((size_t)B_ * C_ * H_ * W_));
        }
    }
}

extern "C" void kernel_launch(void* const* d_in, const int* in_sizes, int n_in,
                              void* d_out, int out_size)
{
    const float* in = (const float*)d_in[0];
    float* out = (float*)d_out;

    dim3 grid(W_ / TILE, H_ / TILE, B_);   // 16,16,8
    blt_loss_kernel<<<grid, NT>>>(in, out);
}